// round 15
// baseline (speedup 1.0000x reference)
#include <cuda_runtime.h>
#include <cuda_bf16.h>
#include <cuda_fp16.h>
#include <cstdint>

#define N_NODES 50000
#define N_EDGES 800000
#define HD 256          // NUM_HEADS * OUT_DIM
#define K_DIM 256       // IN_DIM
#define N_SCAN_BLOCKS ((N_NODES + 1023) / 1024)   // 49

// ---------------- scratch (device globals; no allocation allowed) ----------
__device__ __align__(16) float  g_Wh[(size_t)N_NODES * HD];    // 51.2 MB fp32 (exact)
__device__ __align__(16) __half g_Whh[(size_t)N_NODES * HD];   // 25.6 MB fp16 gather mirror
__device__ float4 g_st[N_NODES];        // (s0, s1, t0, t1) per node
__device__ int    g_deg[N_NODES];
__device__ int    g_off[N_NODES + 1];
__device__ int    g_cursor[N_NODES];
__device__ int    g_csr_dst[N_EDGES];
__device__ int    g_bsum[64];
__device__ int    g_is64;               // 1 if edge_index delivered as int64

// ---------------- helpers ---------------------------------------------------
__device__ __forceinline__ int clamp_node(int v) {
    v = v < 0 ? 0 : v;
    return v >= N_NODES ? N_NODES - 1 : v;
}
__device__ __forceinline__ int edge_src(const int* e32, int i, int is64) {
    return clamp_node(is64 ? e32[2 * i] : e32[i]);
}
__device__ __forceinline__ int edge_dst(const int* e32, int i, int is64) {
    return clamp_node(is64 ? e32[2 * (N_EDGES + i)] : e32[N_EDGES + i]);
}

__device__ __forceinline__ void ldsm_x4(uint32_t (&r)[4], const void* p) {
    uint32_t addr = (uint32_t)__cvta_generic_to_shared(p);
    asm volatile("ldmatrix.sync.aligned.m8n8.x4.shared.b16 {%0,%1,%2,%3}, [%4];"
                 : "=r"(r[0]), "=r"(r[1]), "=r"(r[2]), "=r"(r[3]) : "r"(addr));
}
__device__ __forceinline__ void ldsm_x4t(uint32_t (&r)[4], const void* p) {
    uint32_t addr = (uint32_t)__cvta_generic_to_shared(p);
    asm volatile("ldmatrix.sync.aligned.m8n8.x4.trans.shared.b16 {%0,%1,%2,%3}, [%4];"
                 : "=r"(r[0]), "=r"(r[1]), "=r"(r[2]), "=r"(r[3]) : "r"(addr));
}
__device__ __forceinline__ void mma16816(float (&d)[4], const uint32_t (&a)[4],
                                         uint32_t b0, uint32_t b1) {
    asm volatile(
        "mma.sync.aligned.m16n8k16.row.col.f32.bf16.bf16.f32 "
        "{%0,%1,%2,%3}, {%4,%5,%6,%7}, {%8,%9}, {%0,%1,%2,%3};"
        : "+f"(d[0]), "+f"(d[1]), "+f"(d[2]), "+f"(d[3])
        : "r"(a[0]), "r"(a[1]), "r"(a[2]), "r"(a[3]), "r"(b0), "r"(b1));
}
__device__ __forceinline__ void split_bf(float v, __nv_bfloat16& h, __nv_bfloat16& l) {
    h = __float2bfloat16(v);
    l = __float2bfloat16(v - __bfloat162float(h));
}

// ---------------- 0) zero degree + st arrays, dtype probe -------------------
__global__ void init_kernel(const int* __restrict__ e32) {
    int i = blockIdx.x * blockDim.x + threadIdx.x;
    if (i < N_NODES) {
        g_deg[i] = 0;
        g_st[i] = make_float4(0.f, 0.f, 0.f, 0.f);
    }
    if (i == 0) {
        int is64 = 1;
        for (int k = 0; k < 256; k++) {
            if (e32[2 * k + 1] != 0) { is64 = 0; break; }
        }
        g_is64 = is64;
    }
}

// ---------------- 1) GEMM: Wh = x @ W + b via bf16 hi/lo tensor cores ------
// 3-pass split precision: x@W = xh@Wh' + xh@Wl + xl@Wh' (lo*lo dropped, ~2^-18)
// Epilogue: + bias, store fp32 Wh + fp16 mirror, accumulate s/t into g_st.
#define BM 128
#define BN 128
#define BKF 32           // fp32 K per chunk
#define APAD 40          // A smem row stride (bf16)
#define BPAD 136         // B smem row stride (bf16)

__global__ __launch_bounds__(256) void gemm_bf16_kernel(
    const float* __restrict__ A,     // [50000, 256]
    const float* __restrict__ B,     // [256, 256]
    const float* __restrict__ bias,  // [256]
    const float* __restrict__ avec)  // [256] = [a_src(128) | a_dst(128)]
{
    __shared__ __align__(16) __nv_bfloat16 AsH[BM][APAD];
    __shared__ __align__(16) __nv_bfloat16 AsL[BM][APAD];
    __shared__ __align__(16) __nv_bfloat16 BsH[BKF][BPAD];
    __shared__ __align__(16) __nv_bfloat16 BsL[BKF][BPAD];

    const int tid  = threadIdx.x;
    const int lane = tid & 31;
    const int wid  = tid >> 5;
    const int bRow = blockIdx.x * BM;
    const int bCol = blockIdx.y * BN;

    const int warp_m = wid & 3;   // 4 warps over M (32 rows each)
    const int warp_n = wid >> 2;  // 2 warps over N (64 cols each)
    const int rows0 = warp_m * 32;
    const int cols0 = warp_n * 64;

    float acc[2][8][4];
#pragma unroll
    for (int mi = 0; mi < 2; mi++)
#pragma unroll
        for (int nf = 0; nf < 8; nf++)
#pragma unroll
            for (int q = 0; q < 4; q++) acc[mi][nf][q] = 0.0f;

    const int ar = tid >> 1;
    const int ac = (tid & 1) * 16;
    const int br = tid >> 3;
    const int bc = (tid & 7) * 16;

    for (int k0 = 0; k0 < K_DIM; k0 += BKF) {
        // ---- load + convert A tile (128 x 32 fp32 -> hi/lo bf16) ----
        {
            int gr = bRow + ar;
            const float* Ap = A + (size_t)gr * K_DIM + k0 + ac;
#pragma unroll
            for (int q = 0; q < 4; q++) {
                float4 v = make_float4(0.f, 0.f, 0.f, 0.f);
                if (gr < N_NODES) v = *(const float4*)(Ap + q * 4);
                __nv_bfloat16 h0, l0, h1, l1, h2, l2, h3, l3;
                split_bf(v.x, h0, l0); split_bf(v.y, h1, l1);
                split_bf(v.z, h2, l2); split_bf(v.w, h3, l3);
                int c = ac + q * 4;
                *(__nv_bfloat162*)&AsH[ar][c]     = __nv_bfloat162(h0, h1);
                *(__nv_bfloat162*)&AsH[ar][c + 2] = __nv_bfloat162(h2, h3);
                *(__nv_bfloat162*)&AsL[ar][c]     = __nv_bfloat162(l0, l1);
                *(__nv_bfloat162*)&AsL[ar][c + 2] = __nv_bfloat162(l2, l3);
            }
        }
        // ---- load + convert B tile (32 x 128 fp32 -> hi/lo bf16) ----
        {
            const float* Bp = B + (size_t)(k0 + br) * HD + bCol + bc;
#pragma unroll
            for (int q = 0; q < 4; q++) {
                float4 v = *(const float4*)(Bp + q * 4);
                __nv_bfloat16 h0, l0, h1, l1, h2, l2, h3, l3;
                split_bf(v.x, h0, l0); split_bf(v.y, h1, l1);
                split_bf(v.z, h2, l2); split_bf(v.w, h3, l3);
                int c = bc + q * 4;
                *(__nv_bfloat162*)&BsH[br][c]     = __nv_bfloat162(h0, h1);
                *(__nv_bfloat162*)&BsH[br][c + 2] = __nv_bfloat162(h2, h3);
                *(__nv_bfloat162*)&BsL[br][c]     = __nv_bfloat162(l0, l1);
                *(__nv_bfloat162*)&BsL[br][c + 2] = __nv_bfloat162(l2, l3);
            }
        }
        __syncthreads();

        // ---- 3 passes: (Ah,Bh), (Ah,Bl), (Al,Bh) ----
#pragma unroll
        for (int pass = 0; pass < 3; pass++) {
            const __nv_bfloat16 (*Ap)[APAD] = (pass == 2) ? AsL : AsH;
            const __nv_bfloat16 (*Bp)[BPAD] = (pass == 1) ? BsL : BsH;
#pragma unroll
            for (int k16 = 0; k16 < BKF; k16 += 16) {
                uint32_t afrag[2][4];
#pragma unroll
                for (int mi = 0; mi < 2; mi++)
                    ldsm_x4(afrag[mi],
                            &Ap[rows0 + mi * 16 + (lane & 15)][k16 + (lane >> 4) * 8]);
                uint32_t bfrag[4][4];
#pragma unroll
                for (int nb = 0; nb < 4; nb++)
                    ldsm_x4t(bfrag[nb],
                             &Bp[k16 + (lane & 15)][cols0 + nb * 16 + (lane >> 4) * 8]);
#pragma unroll
                for (int mi = 0; mi < 2; mi++)
#pragma unroll
                    for (int nb = 0; nb < 4; nb++) {
                        mma16816(acc[mi][2 * nb],     afrag[mi], bfrag[nb][0], bfrag[nb][1]);
                        mma16816(acc[mi][2 * nb + 1], afrag[mi], bfrag[nb][2], bfrag[nb][3]);
                    }
            }
        }
        __syncthreads();
    }

    // ---- epilogue: + bias, store fp32 + fp16 mirror, accumulate s/t -------
    const int qrow = lane >> 2;
    const int qcol = (lane & 3) * 2;
    const int head = (bCol + cols0) >> 7;   // 0 or 1 (64-col span never straddles heads)
#pragma unroll
    for (int mi = 0; mi < 2; mi++) {
        int row0 = bRow + rows0 + mi * 16 + qrow;
        int row1 = row0 + 8;
        float s0 = 0.f, t0 = 0.f, s1 = 0.f, t1 = 0.f;
#pragma unroll
        for (int nf = 0; nf < 8; nf++) {
            int col = bCol + cols0 + nf * 8 + qcol;
            float b0 = bias[col], b1 = bias[col + 1];
            int d0 = col & 127;
            float as0 = avec[d0],       as1 = avec[d0 + 1];
            float at0 = avec[128 + d0], at1 = avec[128 + d0 + 1];
            float o00 = acc[mi][nf][0] + b0, o01 = acc[mi][nf][1] + b1;
            float o10 = acc[mi][nf][2] + b0, o11 = acc[mi][nf][3] + b1;
            s0 += o00 * as0 + o01 * as1;  t0 += o00 * at0 + o01 * at1;
            s1 += o10 * as0 + o11 * as1;  t1 += o10 * at0 + o11 * at1;
            if (row0 < N_NODES) {
                *(float2*)(g_Wh + (size_t)row0 * HD + col) = make_float2(o00, o01);
                *(__half2*)(g_Whh + (size_t)row0 * HD + col) = __floats2half2_rn(o00, o01);
            }
            if (row1 < N_NODES) {
                *(float2*)(g_Wh + (size_t)row1 * HD + col) = make_float2(o10, o11);
                *(__half2*)(g_Whh + (size_t)row1 * HD + col) = __floats2half2_rn(o10, o11);
            }
        }
        // reduce over the 4 lanes of each quad-row (lanes 4k..4k+3 share rows)
#pragma unroll
        for (int o = 1; o <= 2; o <<= 1) {
            s0 += __shfl_xor_sync(0xffffffffu, s0, o);
            t0 += __shfl_xor_sync(0xffffffffu, t0, o);
            s1 += __shfl_xor_sync(0xffffffffu, s1, o);
            t1 += __shfl_xor_sync(0xffffffffu, t1, o);
        }
        if ((lane & 3) == 0) {
            if (row0 < N_NODES) {
                atomicAdd(&((float*)&g_st[row0])[head],     s0);
                atomicAdd(&((float*)&g_st[row0])[2 + head], t0);
            }
            if (row1 < N_NODES) {
                atomicAdd(&((float*)&g_st[row1])[head],     s1);
                atomicAdd(&((float*)&g_st[row1])[2 + head], t1);
            }
        }
    }
}

// ---------------- 3) degree histogram --------------------------------------
__global__ void degree_kernel(const int* __restrict__ e32) {
    int i = blockIdx.x * blockDim.x + threadIdx.x;
    if (i >= N_EDGES) return;
    int is64 = g_is64;
    atomicAdd(&g_deg[edge_src(e32, i, is64)], 1);
}

// ---------------- 4) multi-block exclusive scan ----------------------------
__global__ __launch_bounds__(1024) void scan_blocks_kernel() {
    __shared__ int sm[1024];
    int i = blockIdx.x * 1024 + threadIdx.x;
    int v = (i < N_NODES) ? g_deg[i] : 0;
    sm[threadIdx.x] = v;
    __syncthreads();
#pragma unroll
    for (int o = 1; o < 1024; o <<= 1) {
        int t = (threadIdx.x >= (unsigned)o) ? sm[threadIdx.x - o] : 0;
        __syncthreads();
        sm[threadIdx.x] += t;
        __syncthreads();
    }
    if (i < N_NODES) g_off[i] = sm[threadIdx.x] - v;   // local exclusive
    if (threadIdx.x == 1023) g_bsum[blockIdx.x] = sm[1023];
}

__global__ void scan_tops_kernel() {
    if (threadIdx.x == 0 && blockIdx.x == 0) {
        int run = 0;
        for (int b = 0; b < N_SCAN_BLOCKS; b++) {
            int v = g_bsum[b];
            g_bsum[b] = run;
            run += v;
        }
        g_off[N_NODES] = run;
    }
}

__global__ void scan_add_kernel() {
    int i = blockIdx.x * blockDim.x + threadIdx.x;
    if (i >= N_NODES) return;
    int val = g_off[i] + g_bsum[i >> 10];
    g_off[i]    = val;
    g_cursor[i] = val;
}

// ---------------- 5) scatter edges into CSR --------------------------------
__global__ void scatter_kernel(const int* __restrict__ e32) {
    int i = blockIdx.x * blockDim.x + threadIdx.x;
    if (i >= N_EDGES) return;
    int is64 = g_is64;
    int s = edge_src(e32, i, is64);
    int d = edge_dst(e32, i, is64);
    int pos = atomicAdd(&g_cursor[s], 1);
    if (pos < N_EDGES) g_csr_dst[pos] = d;
}

// ---------------- 6) per-node softmax aggregation (warp per node) ----------
// Gathers the fp16 mirror (half traffic); accumulates fp32.
__global__ __launch_bounds__(256) void agg_kernel(float* __restrict__ out) {
    int n    = (blockIdx.x * blockDim.x + threadIdx.x) >> 5;
    int lane = threadIdx.x & 31;
    if (n >= N_NODES) return;

    int off0 = g_off[n];
    int deg  = g_off[n + 1] - off0;
    int c4   = lane * 2;    // float4 index within row of 64 float4s
    const float4* wh4  = (const float4*)g_Wh;
    const uint4*  whh4 = (const uint4*)g_Whh;   // 16B = 8 halves; row = 32 uint4
    float4* out4 = (float4*)out;

    if (deg == 0) {
        out4[(size_t)n * 64 + c4]     = wh4[(size_t)n * 64 + c4];
        out4[(size_t)n * 64 + c4 + 1] = wh4[(size_t)n * 64 + c4 + 1];
        return;
    }

    float4 stn = g_st[n];
    int   h    = lane >> 4;
    float s_me = h ? stn.y : stn.x;

    // phase A: per-head max over this node's edges (parallel over lanes)
    float m0 = -1e30f, m1 = -1e30f;
    for (int j = lane; j < deg; j += 32) {
        int d = __ldg(&g_csr_dst[off0 + j]);
        float4 td = __ldg(&g_st[d]);
        float e0 = stn.x + td.z; e0 = e0 > 0.f ? e0 : 0.2f * e0;
        float e1 = stn.y + td.w; e1 = e1 > 0.f ? e1 : 0.2f * e1;
        m0 = fmaxf(m0, e0);
        m1 = fmaxf(m1, e1);
    }
#pragma unroll
    for (int o = 16; o >= 1; o >>= 1) {
        m0 = fmaxf(m0, __shfl_xor_sync(0xffffffffu, m0, o));
        m1 = fmaxf(m1, __shfl_xor_sync(0xffffffffu, m1, o));
    }
    float m_me = h ? m1 : m0;

    // phase B: fused exp-sum + weighted accumulation, software-pipelined
    float acc0 = 0.f, acc1 = 0.f, acc2 = 0.f, acc3 = 0.f;
    float acc4 = 0.f, acc5 = 0.f, acc6 = 0.f, acc7 = 0.f;
    float denom = 0.f;

    int d_cur = __ldg(&g_csr_dst[off0]);
    float4 td_cur = __ldg(&g_st[d_cur]);
    uint4  hv_cur = __ldg(&whh4[(size_t)d_cur * 32 + lane]);

    for (int j = 0; j < deg; j++) {
        float4 td = td_cur;
        uint4  hv = hv_cur;
        if (j + 1 < deg) {
            int dn = __ldg(&g_csr_dst[off0 + j + 1]);
            td_cur = __ldg(&g_st[dn]);
            hv_cur = __ldg(&whh4[(size_t)dn * 32 + lane]);
        }
        float t_me = h ? td.w : td.z;
        float e = s_me + t_me;
        e = e > 0.f ? e : 0.2f * e;
        float w = __expf(e - m_me);
        denom += w;
        float2 f0 = __half22float2(*(__half2*)&hv.x);
        float2 f1 = __half22float2(*(__half2*)&hv.y);
        float2 f2 = __half22float2(*(__half2*)&hv.z);
        float2 f3 = __half22float2(*(__half2*)&hv.w);
        acc0 += w * f0.x; acc1 += w * f0.y; acc2 += w * f1.x; acc3 += w * f1.y;
        acc4 += w * f2.x; acc5 += w * f2.y; acc6 += w * f3.x; acc7 += w * f3.y;
    }
    float inv = 1.0f / denom;
    float4 o0 = make_float4(acc0 * inv, acc1 * inv, acc2 * inv, acc3 * inv);
    float4 o1 = make_float4(acc4 * inv, acc5 * inv, acc6 * inv, acc7 * inv);
    out4[(size_t)n * 64 + c4]     = o0;
    out4[(size_t)n * 64 + c4 + 1] = o1;
}

// ---------------- launch: CSR build overlapped with GEMM --------------------
extern "C" void kernel_launch(void* const* d_in, const int* in_sizes, int n_in,
                              void* d_out, int out_size) {
    const float* x   = (const float*)d_in[0];
    const int*   e32 = (const int*)d_in[1];   // int32 view; dtype probed at runtime
    const float* Ww  = (const float*)d_in[2];
    const float* Wb  = (const float*)d_in[3];
    const float* a   = (const float*)d_in[4];
    float* out = (float*)d_out;

    // one-time host-side resources (no device memory; created on the
    // non-captured correctness call, reused identically during capture)
    static cudaStream_t s2 = nullptr;
    static cudaEvent_t  evFork = nullptr, evJoin = nullptr;
    if (!s2) {
        cudaStreamCreateWithFlags(&s2, cudaStreamNonBlocking);
        cudaEventCreateWithFlags(&evFork, cudaEventDisableTiming);
        cudaEventCreateWithFlags(&evJoin, cudaEventDisableTiming);
    }

    init_kernel<<<(N_NODES + 255) / 256, 256>>>(e32);
    cudaEventRecord(evFork, 0);
    cudaStreamWaitEvent(s2, evFork, 0);

    // stream s2: CSR build (depends only on edge_index + zeroed g_deg)
    degree_kernel<<<(N_EDGES + 255) / 256, 256, 0, s2>>>(e32);
    scan_blocks_kernel<<<N_SCAN_BLOCKS, 1024, 0, s2>>>();
    scan_tops_kernel<<<1, 32, 0, s2>>>();
    scan_add_kernel<<<(N_NODES + 255) / 256, 256, 0, s2>>>();
    scatter_kernel<<<(N_EDGES + 255) / 256, 256, 0, s2>>>(e32);
    cudaEventRecord(evJoin, s2);

    // stream 0 (concurrent): GEMM + fused s/t projection + fp16 mirror
    gemm_bf16_kernel<<<dim3((N_NODES + BM - 1) / BM, HD / BN), 256>>>(x, Ww, Wb, a);

    cudaStreamWaitEvent(0, evJoin, 0);
    agg_kernel<<<(N_NODES * 32 + 255) / 256, 256>>>(out);
}

// round 16
// speedup vs baseline: 1.5626x; 1.5626x over previous
#include <cuda_runtime.h>
#include <cuda_bf16.h>
#include <cuda_fp16.h>
#include <cstdint>

#define N_NODES 50000
#define N_EDGES 800000
#define HD 256          // NUM_HEADS * OUT_DIM
#define K_DIM 256       // IN_DIM
#define N_SCAN_BLOCKS ((N_NODES + 1023) / 1024)   // 49

// ---------------- scratch (device globals; no allocation allowed) ----------
__device__ __align__(16) __half g_Whh[(size_t)N_NODES * HD];   // 25.6 MB fp16 Wh
__device__ float4 g_st[N_NODES];        // (s0, s1, t0, t1) per node
__device__ int    g_deg[N_NODES];
__device__ int    g_off[N_NODES + 1];
__device__ int    g_cursor[N_NODES];
__device__ int    g_csr_dst[N_EDGES];
__device__ int    g_bsum[64];
__device__ int    g_is64;               // 1 if edge_index delivered as int64

// ---------------- helpers ---------------------------------------------------
__device__ __forceinline__ int clamp_node(int v) {
    v = v < 0 ? 0 : v;
    return v >= N_NODES ? N_NODES - 1 : v;
}
__device__ __forceinline__ int edge_src(const int* e32, int i, int is64) {
    return clamp_node(is64 ? e32[2 * i] : e32[i]);
}
__device__ __forceinline__ int edge_dst(const int* e32, int i, int is64) {
    return clamp_node(is64 ? e32[2 * (N_EDGES + i)] : e32[N_EDGES + i]);
}

__device__ __forceinline__ void ldsm_x4(uint32_t (&r)[4], const void* p) {
    uint32_t addr = (uint32_t)__cvta_generic_to_shared(p);
    asm volatile("ldmatrix.sync.aligned.m8n8.x4.shared.b16 {%0,%1,%2,%3}, [%4];"
                 : "=r"(r[0]), "=r"(r[1]), "=r"(r[2]), "=r"(r[3]) : "r"(addr));
}
__device__ __forceinline__ void ldsm_x4t(uint32_t (&r)[4], const void* p) {
    uint32_t addr = (uint32_t)__cvta_generic_to_shared(p);
    asm volatile("ldmatrix.sync.aligned.m8n8.x4.trans.shared.b16 {%0,%1,%2,%3}, [%4];"
                 : "=r"(r[0]), "=r"(r[1]), "=r"(r[2]), "=r"(r[3]) : "r"(addr));
}
__device__ __forceinline__ void mma16816(float (&d)[4], const uint32_t (&a)[4],
                                         uint32_t b0, uint32_t b1) {
    asm volatile(
        "mma.sync.aligned.m16n8k16.row.col.f32.bf16.bf16.f32 "
        "{%0,%1,%2,%3}, {%4,%5,%6,%7}, {%8,%9}, {%0,%1,%2,%3};"
        : "+f"(d[0]), "+f"(d[1]), "+f"(d[2]), "+f"(d[3])
        : "r"(a[0]), "r"(a[1]), "r"(a[2]), "r"(a[3]), "r"(b0), "r"(b1));
}
__device__ __forceinline__ void split_bf(float v, __nv_bfloat16& h, __nv_bfloat16& l) {
    h = __float2bfloat16(v);
    l = __float2bfloat16(v - __bfloat162float(h));
}

// ---------------- 0) zero degree + st arrays, dtype probe -------------------
__global__ void init_kernel(const int* __restrict__ e32) {
    int i = blockIdx.x * blockDim.x + threadIdx.x;
    if (i < N_NODES) {
        g_deg[i] = 0;
        g_st[i] = make_float4(0.f, 0.f, 0.f, 0.f);
    }
    if (i == 0) {
        int is64 = 1;
        for (int k = 0; k < 256; k++) {
            if (e32[2 * k + 1] != 0) { is64 = 0; break; }
        }
        g_is64 = is64;
    }
}

// ---------------- 1) GEMM: Wh = x @ W + b via bf16 hi/lo tensor cores ------
// 3-pass split precision: x@W = xh@Wh' + xh@Wl + xl@Wh' (lo*lo dropped, ~2^-18)
// Epilogue: + bias, store fp16 Wh mirror, accumulate s/t into g_st (fp32).
#define BM 128
#define BN 128
#define BKF 32           // fp32 K per chunk
#define APAD 40          // A smem row stride (bf16)
#define BPAD 136         // B smem row stride (bf16)

__global__ __launch_bounds__(256) void gemm_bf16_kernel(
    const float* __restrict__ A,     // [50000, 256]
    const float* __restrict__ B,     // [256, 256]
    const float* __restrict__ bias,  // [256]
    const float* __restrict__ avec)  // [256] = [a_src(128) | a_dst(128)]
{
    __shared__ __align__(16) __nv_bfloat16 AsH[BM][APAD];
    __shared__ __align__(16) __nv_bfloat16 AsL[BM][APAD];
    __shared__ __align__(16) __nv_bfloat16 BsH[BKF][BPAD];
    __shared__ __align__(16) __nv_bfloat16 BsL[BKF][BPAD];

    const int tid  = threadIdx.x;
    const int lane = tid & 31;
    const int wid  = tid >> 5;
    const int bRow = blockIdx.x * BM;
    const int bCol = blockIdx.y * BN;

    const int warp_m = wid & 3;   // 4 warps over M (32 rows each)
    const int warp_n = wid >> 2;  // 2 warps over N (64 cols each)
    const int rows0 = warp_m * 32;
    const int cols0 = warp_n * 64;

    float acc[2][8][4];
#pragma unroll
    for (int mi = 0; mi < 2; mi++)
#pragma unroll
        for (int nf = 0; nf < 8; nf++)
#pragma unroll
            for (int q = 0; q < 4; q++) acc[mi][nf][q] = 0.0f;

    const int ar = tid >> 1;
    const int ac = (tid & 1) * 16;
    const int br = tid >> 3;
    const int bc = (tid & 7) * 16;

    for (int k0 = 0; k0 < K_DIM; k0 += BKF) {
        // ---- load + convert A tile (128 x 32 fp32 -> hi/lo bf16) ----
        {
            int gr = bRow + ar;
            const float* Ap = A + (size_t)gr * K_DIM + k0 + ac;
#pragma unroll
            for (int q = 0; q < 4; q++) {
                float4 v = make_float4(0.f, 0.f, 0.f, 0.f);
                if (gr < N_NODES) v = *(const float4*)(Ap + q * 4);
                __nv_bfloat16 h0, l0, h1, l1, h2, l2, h3, l3;
                split_bf(v.x, h0, l0); split_bf(v.y, h1, l1);
                split_bf(v.z, h2, l2); split_bf(v.w, h3, l3);
                int c = ac + q * 4;
                *(__nv_bfloat162*)&AsH[ar][c]     = __nv_bfloat162(h0, h1);
                *(__nv_bfloat162*)&AsH[ar][c + 2] = __nv_bfloat162(h2, h3);
                *(__nv_bfloat162*)&AsL[ar][c]     = __nv_bfloat162(l0, l1);
                *(__nv_bfloat162*)&AsL[ar][c + 2] = __nv_bfloat162(l2, l3);
            }
        }
        // ---- load + convert B tile (32 x 128 fp32 -> hi/lo bf16) ----
        {
            const float* Bp = B + (size_t)(k0 + br) * HD + bCol + bc;
#pragma unroll
            for (int q = 0; q < 4; q++) {
                float4 v = *(const float4*)(Bp + q * 4);
                __nv_bfloat16 h0, l0, h1, l1, h2, l2, h3, l3;
                split_bf(v.x, h0, l0); split_bf(v.y, h1, l1);
                split_bf(v.z, h2, l2); split_bf(v.w, h3, l3);
                int c = bc + q * 4;
                *(__nv_bfloat162*)&BsH[br][c]     = __nv_bfloat162(h0, h1);
                *(__nv_bfloat162*)&BsH[br][c + 2] = __nv_bfloat162(h2, h3);
                *(__nv_bfloat162*)&BsL[br][c]     = __nv_bfloat162(l0, l1);
                *(__nv_bfloat162*)&BsL[br][c + 2] = __nv_bfloat162(l2, l3);
            }
        }
        __syncthreads();

        // ---- 3 passes: (Ah,Bh), (Ah,Bl), (Al,Bh) ----
#pragma unroll
        for (int pass = 0; pass < 3; pass++) {
            const __nv_bfloat16 (*Ap)[APAD] = (pass == 2) ? AsL : AsH;
            const __nv_bfloat16 (*Bp)[BPAD] = (pass == 1) ? BsL : BsH;
#pragma unroll
            for (int k16 = 0; k16 < BKF; k16 += 16) {
                uint32_t afrag[2][4];
#pragma unroll
                for (int mi = 0; mi < 2; mi++)
                    ldsm_x4(afrag[mi],
                            &Ap[rows0 + mi * 16 + (lane & 15)][k16 + (lane >> 4) * 8]);
                uint32_t bfrag[4][4];
#pragma unroll
                for (int nb = 0; nb < 4; nb++)
                    ldsm_x4t(bfrag[nb],
                             &Bp[k16 + (lane & 15)][cols0 + nb * 16 + (lane >> 4) * 8]);
#pragma unroll
                for (int mi = 0; mi < 2; mi++)
#pragma unroll
                    for (int nb = 0; nb < 4; nb++) {
                        mma16816(acc[mi][2 * nb],     afrag[mi], bfrag[nb][0], bfrag[nb][1]);
                        mma16816(acc[mi][2 * nb + 1], afrag[mi], bfrag[nb][2], bfrag[nb][3]);
                    }
            }
        }
        __syncthreads();
    }

    // ---- epilogue: + bias, store fp16 mirror, accumulate s/t ---------------
    const int qrow = lane >> 2;
    const int qcol = (lane & 3) * 2;
    const int head = (bCol + cols0) >> 7;   // 0 or 1 (64-col span never straddles heads)
#pragma unroll
    for (int mi = 0; mi < 2; mi++) {
        int row0 = bRow + rows0 + mi * 16 + qrow;
        int row1 = row0 + 8;
        float s0 = 0.f, t0 = 0.f, s1 = 0.f, t1 = 0.f;
#pragma unroll
        for (int nf = 0; nf < 8; nf++) {
            int col = bCol + cols0 + nf * 8 + qcol;
            float b0 = bias[col], b1 = bias[col + 1];
            int d0 = col & 127;
            float as0 = avec[d0],       as1 = avec[d0 + 1];
            float at0 = avec[128 + d0], at1 = avec[128 + d0 + 1];
            float o00 = acc[mi][nf][0] + b0, o01 = acc[mi][nf][1] + b1;
            float o10 = acc[mi][nf][2] + b0, o11 = acc[mi][nf][3] + b1;
            s0 += o00 * as0 + o01 * as1;  t0 += o00 * at0 + o01 * at1;
            s1 += o10 * as0 + o11 * as1;  t1 += o10 * at0 + o11 * at1;
            if (row0 < N_NODES)
                *(__half2*)(g_Whh + (size_t)row0 * HD + col) = __floats2half2_rn(o00, o01);
            if (row1 < N_NODES)
                *(__half2*)(g_Whh + (size_t)row1 * HD + col) = __floats2half2_rn(o10, o11);
        }
        // reduce over the 4 lanes of each quad-row (lanes 4k..4k+3 share rows)
#pragma unroll
        for (int o = 1; o <= 2; o <<= 1) {
            s0 += __shfl_xor_sync(0xffffffffu, s0, o);
            t0 += __shfl_xor_sync(0xffffffffu, t0, o);
            s1 += __shfl_xor_sync(0xffffffffu, s1, o);
            t1 += __shfl_xor_sync(0xffffffffu, t1, o);
        }
        if ((lane & 3) == 0) {
            if (row0 < N_NODES) {
                atomicAdd(&((float*)&g_st[row0])[head],     s0);
                atomicAdd(&((float*)&g_st[row0])[2 + head], t0);
            }
            if (row1 < N_NODES) {
                atomicAdd(&((float*)&g_st[row1])[head],     s1);
                atomicAdd(&((float*)&g_st[row1])[2 + head], t1);
            }
        }
    }
}

// ---------------- 3) degree histogram --------------------------------------
__global__ void degree_kernel(const int* __restrict__ e32) {
    int i = blockIdx.x * blockDim.x + threadIdx.x;
    if (i >= N_EDGES) return;
    int is64 = g_is64;
    atomicAdd(&g_deg[edge_src(e32, i, is64)], 1);
}

// ---------------- 4) multi-block exclusive scan ----------------------------
__global__ __launch_bounds__(1024) void scan_blocks_kernel() {
    __shared__ int sm[1024];
    int i = blockIdx.x * 1024 + threadIdx.x;
    int v = (i < N_NODES) ? g_deg[i] : 0;
    sm[threadIdx.x] = v;
    __syncthreads();
#pragma unroll
    for (int o = 1; o < 1024; o <<= 1) {
        int t = (threadIdx.x >= (unsigned)o) ? sm[threadIdx.x - o] : 0;
        __syncthreads();
        sm[threadIdx.x] += t;
        __syncthreads();
    }
    if (i < N_NODES) g_off[i] = sm[threadIdx.x] - v;   // local exclusive
    if (threadIdx.x == 1023) g_bsum[blockIdx.x] = sm[1023];
}

__global__ void scan_tops_kernel() {
    if (threadIdx.x == 0 && blockIdx.x == 0) {
        int run = 0;
        for (int b = 0; b < N_SCAN_BLOCKS; b++) {
            int v = g_bsum[b];
            g_bsum[b] = run;
            run += v;
        }
        g_off[N_NODES] = run;
    }
}

__global__ void scan_add_kernel() {
    int i = blockIdx.x * blockDim.x + threadIdx.x;
    if (i >= N_NODES) return;
    int val = g_off[i] + g_bsum[i >> 10];
    g_off[i]    = val;
    g_cursor[i] = val;
}

// ---------------- 5) scatter edges into CSR --------------------------------
__global__ void scatter_kernel(const int* __restrict__ e32) {
    int i = blockIdx.x * blockDim.x + threadIdx.x;
    if (i >= N_EDGES) return;
    int is64 = g_is64;
    int s = edge_src(e32, i, is64);
    int d = edge_dst(e32, i, is64);
    int pos = atomicAdd(&g_cursor[s], 1);
    if (pos < N_EDGES) g_csr_dst[pos] = d;
}

// ---------------- 6) per-node softmax aggregation (warp per node) ----------
// Gathers fp16 Wh (512 B/edge); accumulates fp32.
__global__ __launch_bounds__(256) void agg_kernel(float* __restrict__ out) {
    int n    = (blockIdx.x * blockDim.x + threadIdx.x) >> 5;
    int lane = threadIdx.x & 31;
    if (n >= N_NODES) return;

    int off0 = g_off[n];
    int deg  = g_off[n + 1] - off0;
    int c4   = lane * 2;    // float4 index within out row of 64 float4s
    const uint4* whh4 = (const uint4*)g_Whh;   // 16B = 8 halves; row = 32 uint4
    float4* out4 = (float4*)out;

    if (deg == 0) {
        uint4 hv = whh4[(size_t)n * 32 + lane];
        float2 f0 = __half22float2(*(__half2*)&hv.x);
        float2 f1 = __half22float2(*(__half2*)&hv.y);
        float2 f2 = __half22float2(*(__half2*)&hv.z);
        float2 f3 = __half22float2(*(__half2*)&hv.w);
        out4[(size_t)n * 64 + c4]     = make_float4(f0.x, f0.y, f1.x, f1.y);
        out4[(size_t)n * 64 + c4 + 1] = make_float4(f2.x, f2.y, f3.x, f3.y);
        return;
    }

    float4 stn = g_st[n];
    int   h    = lane >> 4;
    float s_me = h ? stn.y : stn.x;

    // phase A: per-head max over this node's edges (parallel over lanes)
    float m0 = -1e30f, m1 = -1e30f;
    for (int j = lane; j < deg; j += 32) {
        int d = __ldg(&g_csr_dst[off0 + j]);
        float4 td = __ldg(&g_st[d]);
        float e0 = stn.x + td.z; e0 = e0 > 0.f ? e0 : 0.2f * e0;
        float e1 = stn.y + td.w; e1 = e1 > 0.f ? e1 : 0.2f * e1;
        m0 = fmaxf(m0, e0);
        m1 = fmaxf(m1, e1);
    }
#pragma unroll
    for (int o = 16; o >= 1; o >>= 1) {
        m0 = fmaxf(m0, __shfl_xor_sync(0xffffffffu, m0, o));
        m1 = fmaxf(m1, __shfl_xor_sync(0xffffffffu, m1, o));
    }
    float m_me = h ? m1 : m0;

    // phase B: fused exp-sum + weighted accumulation, software-pipelined
    float acc0 = 0.f, acc1 = 0.f, acc2 = 0.f, acc3 = 0.f;
    float acc4 = 0.f, acc5 = 0.f, acc6 = 0.f, acc7 = 0.f;
    float denom = 0.f;

    int d_cur = __ldg(&g_csr_dst[off0]);
    float4 td_cur = __ldg(&g_st[d_cur]);
    uint4  hv_cur = __ldg(&whh4[(size_t)d_cur * 32 + lane]);

    for (int j = 0; j < deg; j++) {
        float4 td = td_cur;
        uint4  hv = hv_cur;
        if (j + 1 < deg) {
            int dn = __ldg(&g_csr_dst[off0 + j + 1]);
            td_cur = __ldg(&g_st[dn]);
            hv_cur = __ldg(&whh4[(size_t)dn * 32 + lane]);
        }
        float t_me = h ? td.w : td.z;
        float e = s_me + t_me;
        e = e > 0.f ? e : 0.2f * e;
        float w = __expf(e - m_me);
        denom += w;
        float2 f0 = __half22float2(*(__half2*)&hv.x);
        float2 f1 = __half22float2(*(__half2*)&hv.y);
        float2 f2 = __half22float2(*(__half2*)&hv.z);
        float2 f3 = __half22float2(*(__half2*)&hv.w);
        acc0 += w * f0.x; acc1 += w * f0.y; acc2 += w * f1.x; acc3 += w * f1.y;
        acc4 += w * f2.x; acc5 += w * f2.y; acc6 += w * f3.x; acc7 += w * f3.y;
    }
    float inv = 1.0f / denom;
    float4 o0 = make_float4(acc0 * inv, acc1 * inv, acc2 * inv, acc3 * inv);
    float4 o1 = make_float4(acc4 * inv, acc5 * inv, acc6 * inv, acc7 * inv);
    out4[(size_t)n * 64 + c4]     = o0;
    out4[(size_t)n * 64 + c4 + 1] = o1;
}

// ---------------- launch: CSR build overlapped with GEMM --------------------
extern "C" void kernel_launch(void* const* d_in, const int* in_sizes, int n_in,
                              void* d_out, int out_size) {
    const float* x   = (const float*)d_in[0];
    const int*   e32 = (const int*)d_in[1];   // int32 view; dtype probed at runtime
    const float* Ww  = (const float*)d_in[2];
    const float* Wb  = (const float*)d_in[3];
    const float* a   = (const float*)d_in[4];
    float* out = (float*)d_out;

    // one-time host-side resources (no device memory; created on the
    // non-captured correctness call, reused identically during capture)
    static cudaStream_t s2 = nullptr;
    static cudaEvent_t  evFork = nullptr, evJoin = nullptr;
    if (!s2) {
        cudaStreamCreateWithFlags(&s2, cudaStreamNonBlocking);
        cudaEventCreateWithFlags(&evFork, cudaEventDisableTiming);
        cudaEventCreateWithFlags(&evJoin, cudaEventDisableTiming);
    }

    init_kernel<<<(N_NODES + 255) / 256, 256>>>(e32);
    cudaEventRecord(evFork, 0);
    cudaStreamWaitEvent(s2, evFork, 0);

    // stream s2: CSR build (depends only on edge_index + zeroed g_deg)
    degree_kernel<<<(N_EDGES + 255) / 256, 256, 0, s2>>>(e32);
    scan_blocks_kernel<<<N_SCAN_BLOCKS, 1024, 0, s2>>>();
    scan_tops_kernel<<<1, 32, 0, s2>>>();
    scan_add_kernel<<<(N_NODES + 255) / 256, 256, 0, s2>>>();
    scatter_kernel<<<(N_EDGES + 255) / 256, 256, 0, s2>>>(e32);
    cudaEventRecord(evJoin, s2);

    // stream 0 (concurrent): GEMM + fused s/t projection + fp16 mirror
    gemm_bf16_kernel<<<dim3((N_NODES + BM - 1) / BM, HD / BN), 256>>>(x, Ww, Wb, a);

    cudaStreamWaitEvent(0, evJoin, 0);
    agg_kernel<<<(N_NODES * 32 + 255) / 256, 256>>>(out);
}